// round 14
// baseline (speedup 1.0000x reference)
#include <cuda_runtime.h>
#include <math.h>
#include <cstdint>

// memory: [B=256, M=8192, W=32] f32 ; keys: [B,H=4,W=32] ; strengths: [B,H]
// out[b,h,m] = softmax_M( dot/(kn*mn+eps) * softplus(strength) )
// |cos|<1 -> v <= beta: softmax shifted by beta -> associative sum ->
// split M across blocks; partial sums in __device__ array; k2 rescales.
// k1: LDS keys (occ 6), MLP-8 mainloop (8 front-batched LDG.128 per iter).

#define NB      256
#define MM      8192
#define WW      32
#define HH      4
#define EPSF    1e-5f
#define SPLITS  16
#define NT1     256
#define ROWS_PER_BLOCK (MM / SPLITS)                 // 512
#define NWARPS  (NT1 / 32)                           // 8
#define ROWS_PER_WARP  (ROWS_PER_BLOCK / NWARPS)     // 64
#define ITERS   (ROWS_PER_WARP / 8)                  // 8 (8 rows / group)

__device__ float g_partial[NB * HH * SPLITS];

// un-hoistable shared load: keeps key data out of the register file
__device__ __forceinline__ float4 lds128(uint32_t addr) {
    float4 v;
    asm volatile("ld.shared.v4.f32 {%0,%1,%2,%3}, [%4];"
        : "=f"(v.x), "=f"(v.y), "=f"(v.z), "=f"(v.w) : "r"(addr));
    return v;
}

__global__ __launch_bounds__(NT1, 6)
void weightfn_k1(const float* __restrict__ mem,
                 const float* __restrict__ keys,
                 const float* __restrict__ strengths,
                 float* __restrict__ out)
{
    __shared__ float4 sk4[HH][WW / 4];   // keys, [h][chunk]
    __shared__ float  skn[HH];
    __shared__ float  sbeta[HH];
    __shared__ float  sred[NWARPS][4];

    const int bidx = blockIdx.x;
    const int b    = bidx >> 4;              // / SPLITS
    const int seg  = bidx & (SPLITS - 1);
    const int tid  = threadIdx.x;
    const int lane = tid & 31;
    const int wid  = tid >> 5;
    const int sub  = lane & 3;               // quarter of row / h index
    const int g    = lane >> 2;              // row within 8-row group

    if (tid < HH * WW)
        ((float*)sk4)[tid] = keys[b * HH * WW + tid];
    __syncthreads();
    if (tid < HH) {
        float s = strengths[b * HH + tid];
        sbeta[tid] = (s > 20.0f) ? s : log1pf(__expf(s));
        const float* k = (const float*)sk4[tid];
        float sq = 0.0f;
        #pragma unroll
        for (int w = 0; w < WW; w++) sq = fmaf(k[w], k[w], sq);
        skn[tid] = sqrtf(sq + EPSF);
    }
    __syncthreads();

    const float beta_h = sbeta[sub];
    const float kn_h   = skn[sub];

    const uint32_t skbase =
        (uint32_t)__cvta_generic_to_shared(&sk4[0][0]) + (uint32_t)(sub * 32);

    const float4* mp4 = (const float4*)mem + (size_t)b * MM * (WW / 4);
    float* ob = out + (size_t)b * HH * MM;

    const int warpRow0 = seg * ROWS_PER_BLOCK + wid * ROWS_PER_WARP;
    float lsum = 0.0f;

    #pragma unroll
    for (int i = 0; i < ITERS; i += 4) {
        const int row0 = warpRow0 + i * 8 + g;
        // 8 LDG.128 front-batched (MLP 8): 4 row-groups x 2 chunks
        float4 L[4][2];
        #pragma unroll
        for (int r = 0; r < 4; r++) {
            L[r][0] = __ldcs(&mp4[(row0 + r * 8) * 8 + sub * 2]);
            L[r][1] = __ldcs(&mp4[(row0 + r * 8) * 8 + sub * 2 + 1]);
        }

        float sq[4], dot[4][HH];
        #pragma unroll
        for (int r = 0; r < 4; r++) {
            const float4 m0 = L[r][0], m1 = L[r][1];
            float s = fmaf(m0.x, m0.x, fmaf(m0.y, m0.y,
                      fmaf(m0.z, m0.z, fmaf(m0.w, m0.w, 0.0f))));
            s = fmaf(m1.x, m1.x, fmaf(m1.y, m1.y,
                fmaf(m1.z, m1.z, fmaf(m1.w, m1.w, s))));
            sq[r] = s;
        }
        #pragma unroll
        for (int h = 0; h < HH; h++) {
            const float4 k0 = lds128(skbase + (uint32_t)(h * 128));
            const float4 k1 = lds128(skbase + (uint32_t)(h * 128 + 16));
            #pragma unroll
            for (int r = 0; r < 4; r++) {
                const float4 m0 = L[r][0], m1 = L[r][1];
                float d = fmaf(m0.x, k0.x, fmaf(m0.y, k0.y,
                          fmaf(m0.z, k0.z, fmaf(m0.w, k0.w, 0.0f))));
                d = fmaf(m1.x, k1.x, fmaf(m1.y, k1.y,
                    fmaf(m1.z, k1.z, fmaf(m1.w, k1.w, d))));
                dot[r][h] = d;
            }
        }

        #pragma unroll
        for (int mask = 1; mask <= 2; mask <<= 1) {
            #pragma unroll
            for (int r = 0; r < 4; r++) {
                sq[r] += __shfl_xor_sync(0xffffffffu, sq[r], mask);
                #pragma unroll
                for (int h = 0; h < HH; h++)
                    dot[r][h] += __shfl_xor_sync(0xffffffffu, dot[r][h], mask);
            }
        }

        #pragma unroll
        for (int r = 0; r < 4; r++) {
            float d = (sub == 0) ? dot[r][0] : (sub == 1) ? dot[r][1]
                    : (sub == 2) ? dot[r][2] : dot[r][3];
            const float mn = sqrtf(sq[r] + EPSF);
            const float v  = d * __fdividef(beta_h, fmaf(kn_h, mn, EPSF));
            const float e  = __expf(v - beta_h);   // <= 1
            ob[sub * MM + row0 + r * 8] = e;
            lsum += e;
        }
    }

    // sum over 8 lanes sharing this sub (=h)
    #pragma unroll
    for (int mask = 4; mask <= 16; mask <<= 1)
        lsum += __shfl_xor_sync(0xffffffffu, lsum, mask);
    if (lane < 4) sred[wid][lane] = lsum;
    __syncthreads();

    if (tid < 32) {
        float v = sred[tid >> 2][tid & 3];   // 8 warps x 4 h
        #pragma unroll
        for (int mask = 4; mask <= 16; mask <<= 1)
            v += __shfl_xor_sync(0xffffffffu, v, mask);
        if (tid < 4)
            g_partial[(b * HH + tid) * SPLITS + seg] = v;
    }
}

// k2: 2048 blocks x 128 thr; one (b,h,half) per block.
// 8 float4 per thread, all front-batched (L2 hits), then scaled + stcs.
__global__ __launch_bounds__(128)
void weightfn_k2(float* __restrict__ out)
{
    __shared__ float sinv;
    const int bidx = blockIdx.x;
    const int b    = bidx >> 3;
    const int h    = (bidx >> 1) & 3;
    const int half = bidx & 1;
    const int tid  = threadIdx.x;

    float4* o4 = (float4*)out + ((size_t)(b * HH + h) * MM) / 4 + half * 1024;

    // front-batch 8 loads (MLP 8)
    float4 v0 = __ldcg(&o4[tid]);
    float4 v1 = __ldcg(&o4[tid + 128]);
    float4 v2 = __ldcg(&o4[tid + 256]);
    float4 v3 = __ldcg(&o4[tid + 384]);
    float4 v4 = __ldcg(&o4[tid + 512]);
    float4 v5 = __ldcg(&o4[tid + 640]);
    float4 v6 = __ldcg(&o4[tid + 768]);
    float4 v7 = __ldcg(&o4[tid + 896]);

    // warp 0 reduces the 32 partials for this (b,h) in fixed order
    if (tid < 32) {
        float v = g_partial[(b * HH + h) * SPLITS * 2 / 2 + tid];  // SPLITS=16: tid<16 valid
        v = (tid < SPLITS) ? v : 0.0f;
        #pragma unroll
        for (int m = 1; m <= 16; m <<= 1)
            v += __shfl_xor_sync(0xffffffffu, v, m);
        if (tid == 0) sinv = __fdividef(1.0f, v);
    }
    __syncthreads();
    const float inv = sinv;

    v0.x *= inv; v0.y *= inv; v0.z *= inv; v0.w *= inv;
    v1.x *= inv; v1.y *= inv; v1.z *= inv; v1.w *= inv;
    v2.x *= inv; v2.y *= inv; v2.z *= inv; v2.w *= inv;
    v3.x *= inv; v3.y *= inv; v3.z *= inv; v3.w *= inv;
    v4.x *= inv; v4.y *= inv; v4.z *= inv; v4.w *= inv;
    v5.x *= inv; v5.y *= inv; v5.z *= inv; v5.w *= inv;
    v6.x *= inv; v6.y *= inv; v6.z *= inv; v6.w *= inv;
    v7.x *= inv; v7.y *= inv; v7.z *= inv; v7.w *= inv;
    __stcs(&o4[tid],       v0);
    __stcs(&o4[tid + 128], v1);
    __stcs(&o4[tid + 256], v2);
    __stcs(&o4[tid + 384], v3);
    __stcs(&o4[tid + 512], v4);
    __stcs(&o4[tid + 640], v5);
    __stcs(&o4[tid + 768], v6);
    __stcs(&o4[tid + 896], v7);
}

extern "C" void kernel_launch(void* const* d_in, const int* in_sizes, int n_in,
                              void* d_out, int out_size)
{
    const float* mem       = (const float*)d_in[0];
    const float* keys      = (const float*)d_in[1];
    const float* strengths = (const float*)d_in[2];
    float* out             = (float*)d_out;

    weightfn_k1<<<NB * SPLITS, NT1>>>(mem, keys, strengths, out);
    weightfn_k2<<<NB * HH * 2, 128>>>(out);
}

// round 15
// speedup vs baseline: 1.5693x; 1.5693x over previous
#include <cuda_runtime.h>
#include <math.h>
#include <cstdint>

// memory: [B=256, M=8192, W=32] f32 ; keys: [B,H=4,W=32] ; strengths: [B,H]
// out[b,h,m] = softmax_M( dot/(kn*mn+eps) * softplus(strength) )
// |cos|<1 -> v <= beta: softmax shifted by beta -> associative sum ->
// split M across blocks; partials to g_partial; k_mid computes 1024 inverse
// sums; k2 is a sync-free independent-thread rescale.

#define NB      256
#define MM      8192
#define WW      32
#define HH      4
#define EPSF    1e-5f
#define SPLITS  16
#define NT1     256
#define ROWS_PER_BLOCK (MM / SPLITS)                 // 512
#define NWARPS  (NT1 / 32)                           // 8
#define ROWS_PER_WARP  (ROWS_PER_BLOCK / NWARPS)     // 64
#define ITERS   (ROWS_PER_WARP / 8)                  // 8 (8 rows / warp-iter)

__device__ float g_partial[NB * HH * SPLITS];
__device__ float g_inv[NB * HH];

// un-hoistable shared load: keeps key data out of the register file
__device__ __forceinline__ float4 lds128(uint32_t addr) {
    float4 v;
    asm volatile("ld.shared.v4.f32 {%0,%1,%2,%3}, [%4];"
        : "=f"(v.x), "=f"(v.y), "=f"(v.z), "=f"(v.w) : "r"(addr));
    return v;
}

__global__ __launch_bounds__(NT1, 6)
void weightfn_k1(const float* __restrict__ mem,
                 const float* __restrict__ keys,
                 const float* __restrict__ strengths,
                 float* __restrict__ out)
{
    __shared__ float4 sk4[HH][WW / 4];   // keys, [h][chunk]
    __shared__ float  skn[HH];
    __shared__ float  sbeta[HH];
    __shared__ float  sred[NWARPS][4];

    const int bidx = blockIdx.x;
    const int b    = bidx >> 4;              // / SPLITS
    const int seg  = bidx & (SPLITS - 1);
    const int tid  = threadIdx.x;
    const int lane = tid & 31;
    const int wid  = tid >> 5;
    const int sub  = lane & 3;               // quarter of row / h index
    const int g    = lane >> 2;              // row within 8-row group

    if (tid < HH * WW)
        ((float*)sk4)[tid] = keys[b * HH * WW + tid];
    __syncthreads();
    if (tid < HH) {
        float s = strengths[b * HH + tid];
        sbeta[tid] = (s > 20.0f) ? s : log1pf(__expf(s));
        const float* k = (const float*)sk4[tid];
        float sq = 0.0f;
        #pragma unroll
        for (int w = 0; w < WW; w++) sq = fmaf(k[w], k[w], sq);
        skn[tid] = sqrtf(sq + EPSF);
    }
    __syncthreads();

    const float beta_h = sbeta[sub];
    const float kn_h   = skn[sub];

    const uint32_t skbase =
        (uint32_t)__cvta_generic_to_shared(&sk4[0][0]) + (uint32_t)(sub * 32);

    const float4* mp4 = (const float4*)mem + (size_t)b * MM * (WW / 4);
    float* ob = out + (size_t)b * HH * MM;

    const int warpRow0 = seg * ROWS_PER_BLOCK + wid * ROWS_PER_WARP;
    float lsum = 0.0f;

    #pragma unroll
    for (int i = 0; i < ITERS; i += 2) {
        const int rowA = warpRow0 + i * 8 + g;
        const int rowB = rowA + 8;
        // 4 LDG.128 front-batched (MLP 4)
        const float4 a0 = __ldcs(&mp4[rowA * 8 + sub * 2]);
        const float4 a1 = __ldcs(&mp4[rowA * 8 + sub * 2 + 1]);
        const float4 b0 = __ldcs(&mp4[rowB * 8 + sub * 2]);
        const float4 b1 = __ldcs(&mp4[rowB * 8 + sub * 2 + 1]);

        float sqA = fmaf(a0.x, a0.x, fmaf(a0.y, a0.y,
                    fmaf(a0.z, a0.z, fmaf(a0.w, a0.w, 0.0f))));
        sqA = fmaf(a1.x, a1.x, fmaf(a1.y, a1.y,
              fmaf(a1.z, a1.z, fmaf(a1.w, a1.w, sqA))));
        float sqB = fmaf(b0.x, b0.x, fmaf(b0.y, b0.y,
                    fmaf(b0.z, b0.z, fmaf(b0.w, b0.w, 0.0f))));
        sqB = fmaf(b1.x, b1.x, fmaf(b1.y, b1.y,
              fmaf(b1.z, b1.z, fmaf(b1.w, b1.w, sqB))));

        float dotA[HH], dotB[HH];
        #pragma unroll
        for (int h = 0; h < HH; h++) {
            const float4 k0 = lds128(skbase + (uint32_t)(h * 128));
            const float4 k1 = lds128(skbase + (uint32_t)(h * 128 + 16));
            float dA = fmaf(a0.x, k0.x, fmaf(a0.y, k0.y,
                       fmaf(a0.z, k0.z, fmaf(a0.w, k0.w, 0.0f))));
            dA = fmaf(a1.x, k1.x, fmaf(a1.y, k1.y,
                 fmaf(a1.z, k1.z, fmaf(a1.w, k1.w, dA))));
            float dB = fmaf(b0.x, k0.x, fmaf(b0.y, k0.y,
                       fmaf(b0.z, k0.z, fmaf(b0.w, k0.w, 0.0f))));
            dB = fmaf(b1.x, k1.x, fmaf(b1.y, k1.y,
                 fmaf(b1.z, k1.z, fmaf(b1.w, k1.w, dB))));
            dotA[h] = dA;
            dotB[h] = dB;
        }

        #pragma unroll
        for (int mask = 1; mask <= 2; mask <<= 1) {
            sqA += __shfl_xor_sync(0xffffffffu, sqA, mask);
            sqB += __shfl_xor_sync(0xffffffffu, sqB, mask);
            #pragma unroll
            for (int h = 0; h < HH; h++) {
                dotA[h] += __shfl_xor_sync(0xffffffffu, dotA[h], mask);
                dotB[h] += __shfl_xor_sync(0xffffffffu, dotB[h], mask);
            }
        }

        float dA = (sub == 0) ? dotA[0] : (sub == 1) ? dotA[1]
                 : (sub == 2) ? dotA[2] : dotA[3];
        float dB = (sub == 0) ? dotB[0] : (sub == 1) ? dotB[1]
                 : (sub == 2) ? dotB[2] : dotB[3];

        const float mnA = sqrtf(sqA + EPSF);
        const float mnB = sqrtf(sqB + EPSF);
        const float vA = dA * __fdividef(beta_h, fmaf(kn_h, mnA, EPSF));
        const float vB = dB * __fdividef(beta_h, fmaf(kn_h, mnB, EPSF));
        const float eA = __expf(vA - beta_h);
        const float eB = __expf(vB - beta_h);
        ob[sub * MM + rowA] = eA;
        ob[sub * MM + rowB] = eB;
        lsum += eA + eB;
    }

    // sum over 8 lanes sharing this sub (=h)
    #pragma unroll
    for (int mask = 4; mask <= 16; mask <<= 1)
        lsum += __shfl_xor_sync(0xffffffffu, lsum, mask);
    if (lane < 4) sred[wid][lane] = lsum;
    __syncthreads();

    if (tid < 32) {
        float v = sred[tid >> 2][tid & 3];   // 8 warps x 4 h
        #pragma unroll
        for (int mask = 4; mask <= 16; mask <<= 1)
            v += __shfl_xor_sync(0xffffffffu, v, mask);
        if (tid < 4)
            g_partial[(b * HH + tid) * SPLITS + seg] = v;
    }
}

// k_mid: 8 blocks x 128 thr; thread p sums the 16 partials of (b,h)=p in
// fixed order and writes g_inv[p]. 64KB of L2 reads, deterministic.
__global__ __launch_bounds__(128)
void weightfn_kmid(void)
{
    const int p = blockIdx.x * 128 + threadIdx.x;    // 0..1023
    const float* gp = &g_partial[p * SPLITS];
    float s = 0.0f;
    #pragma unroll
    for (int j = 0; j < SPLITS; j++) s += __ldcg(&gp[j]);
    g_inv[p] = __fdividef(1.0f, s);
}

// k2: 2048 blocks x 128 thr; one (b,h,half) per block. NO shared memory,
// NO syncs, NO shfl: every thread independently loads its inv (L2
// broadcast), 8 front-batched ldcg, scale, 8 stcs.
__global__ __launch_bounds__(128)
void weightfn_k2(float* __restrict__ out)
{
    const int bidx = blockIdx.x;
    const int bh   = bidx >> 1;          // (b*HH+h)
    const int half = bidx & 1;
    const int tid  = threadIdx.x;

    float4* o4 = (float4*)out + (size_t)bh * (MM / 4) + half * 1024;

    const float inv = __ldcg(&g_inv[bh]);

    float4 v0 = __ldcg(&o4[tid]);
    float4 v1 = __ldcg(&o4[tid + 128]);
    float4 v2 = __ldcg(&o4[tid + 256]);
    float4 v3 = __ldcg(&o4[tid + 384]);
    float4 v4 = __ldcg(&o4[tid + 512]);
    float4 v5 = __ldcg(&o4[tid + 640]);
    float4 v6 = __ldcg(&o4[tid + 768]);
    float4 v7 = __ldcg(&o4[tid + 896]);

    v0.x *= inv; v0.y *= inv; v0.z *= inv; v0.w *= inv;
    v1.x *= inv; v1.y *= inv; v1.z *= inv; v1.w *= inv;
    v2.x *= inv; v2.y *= inv; v2.z *= inv; v2.w *= inv;
    v3.x *= inv; v3.y *= inv; v3.z *= inv; v3.w *= inv;
    v4.x *= inv; v4.y *= inv; v4.z *= inv; v4.w *= inv;
    v5.x *= inv; v5.y *= inv; v5.z *= inv; v5.w *= inv;
    v6.x *= inv; v6.y *= inv; v6.z *= inv; v6.w *= inv;
    v7.x *= inv; v7.y *= inv; v7.z *= inv; v7.w *= inv;
    __stcs(&o4[tid],       v0);
    __stcs(&o4[tid + 128], v1);
    __stcs(&o4[tid + 256], v2);
    __stcs(&o4[tid + 384], v3);
    __stcs(&o4[tid + 512], v4);
    __stcs(&o4[tid + 640], v5);
    __stcs(&o4[tid + 768], v6);
    __stcs(&o4[tid + 896], v7);
}

extern "C" void kernel_launch(void* const* d_in, const int* in_sizes, int n_in,
                              void* d_out, int out_size)
{
    const float* mem       = (const float*)d_in[0];
    const float* keys      = (const float*)d_in[1];
    const float* strengths = (const float*)d_in[2];
    float* out             = (float*)d_out;

    weightfn_k1<<<NB * SPLITS, NT1>>>(mem, keys, strengths, out);
    weightfn_kmid<<<8, 128>>>();
    weightfn_k2<<<NB * HH * 2, 128>>>(out);
}